// round 4
// baseline (speedup 1.0000x reference)
#include <cuda_runtime.h>
#include <math.h>

// Problem constants
constexpr int cB = 256;   // batch
constexpr int cT = 512;   // timesteps
constexpr int cF = 64;    // features
constexpr int cH = 128;   // hidden
constexpr int cG = 4;     // batch rows per block
constexpr int cNB = cB / cG;   // 64 blocks
constexpr int cNT = 512;       // threads per block

typedef unsigned long long ull;

// Device-global scratch
__device__ float  g_minv[cT];
__device__ float  g_xpart[cNB];
__device__ float  g_ypart[cNB];
// Gate weights repacked: g_W4[i][j] = float4(W[4i..4i+3][j]) for unified k in [0,256)
__device__ float4 g_W4[64 * 512];

// ---------------- packed fp32x2 helpers (Blackwell FFMA2) ----------------
__device__ __forceinline__ ull ffma2(ull a, ull b, ull c) {
    ull d;
    asm("fma.rn.f32x2 %0, %1, %2, %3;" : "=l"(d) : "l"(a), "l"(b), "l"(c));
    return d;
}
__device__ __forceinline__ float upk_sum(ull v) {
    float x, y;
    asm("mov.b64 {%0, %1}, %2;" : "=f"(x), "=f"(y) : "l"(v));
    return x + y;
}

// ---------------- shared memory layout (float offsets, all even) ----------------
constexpr int O_WDH = 0;          // ull[kp<32][j<128]   8192 fl
constexpr int O_WHR = 8192;       // ull[kp<64][f<64]    8192 fl
constexpr int O_WFR = 16384;      // ull[kp<32][f<64]    4096 fl
constexpr int O_WWC = 20480;      // ull[kp<64][f<64]    8192 fl
constexpr int O_BDH = 28672;      // 128
constexpr int O_BHR = 28800;      // 64
constexpr int O_BFR = 28864;      // 64
constexpr int O_BWC = 28928;      // 64
constexpr int O_WDX = 28992;      // 64
constexpr int O_BDX = 29056;      // 64
constexpr int O_BG  = 29120;      // 512 (b_ih+b_hh)
constexpr int O_ACT = 29632;      // [4][256]: cc(64), m(64), h(128)  1024 fl (16B aligned)
constexpr int O_C   = 30656;      // 512
constexpr int O_XBUF= 31168;      // [2][x(256), m(256), d(256)] = 1536
constexpr int O_GX  = 32704;      // 256
constexpr int O_XC  = 32960;      // 256
constexpr int O_G4  = 33216;      // 2048 (gates / reduction scratch)
constexpr int SMEM_FLOATS = O_G4 + 2048;   // 35264 floats = 141056 B

// ---------------------------------------------------------------------------
// Kernel A: per-step mask-sum inverses + gate-weight repack
// ---------------------------------------------------------------------------
__global__ void prep_kernel(const float* __restrict__ masks,
                            const float* __restrict__ W_ih,
                            const float* __restrict__ W_hh) {
    const int t = blockIdx.x;
    const int tid = threadIdx.x;

    int gid = blockIdx.x * 256 + tid;
    if (gid < 64 * 512) {
        int i = gid >> 9;          // k-group 0..63
        int j = gid & 511;         // output 0..511
        const float4* src = (i < 32)
            ? reinterpret_cast<const float4*>(W_ih) + (j * 32 + i)
            : reinterpret_cast<const float4*>(W_hh) + (j * 32 + (i - 32));
        g_W4[i * 512 + j] = *src;
    }

    __shared__ float red[256];
    float s = 0.f;
    for (int i = tid; i < cB * cF; i += 256) {
        int b = i >> 6, f = i & 63;
        s += masks[((long)b * cT + t) * cF + f];
    }
    red[tid] = s;
    __syncthreads();
    for (int o = 128; o > 0; o >>= 1) {
        if (tid < o) red[tid] += red[tid + o];
        __syncthreads();
    }
    if (tid == 0) g_minv[t] = 1.0f / (red[0] + 1e-5f);
}

// ---------------------------------------------------------------------------
// Kernel B: the recurrent scan. One block = 4 batch rows.
// ---------------------------------------------------------------------------
__global__ __launch_bounds__(cNT) void scan_kernel(
    const float* __restrict__ values, const float* __restrict__ masks,
    const float* __restrict__ deltas, const float* __restrict__ labels,
    const float* __restrict__ is_train,
    const float* __restrict__ W_dh, const float* __restrict__ b_dh,
    const float* __restrict__ W_dx, const float* __restrict__ b_dx,
    const float* __restrict__ W_hr, const float* __restrict__ b_hr,
    const float* __restrict__ W_fr, const float* __restrict__ b_fr,
    const float* __restrict__ W_wc, const float* __restrict__ b_wc,
    const float* __restrict__ b_ih, const float* __restrict__ b_hh,
    const float* __restrict__ W_out, const float* __restrict__ b_out,
    float* __restrict__ out)
{
    extern __shared__ __align__(16) float sm[];
    const int tid = threadIdx.x;
    const int b0 = blockIdx.x * cG;

    ull*   wDH = reinterpret_cast<ull*>(sm + O_WDH);
    ull*   wHR = reinterpret_cast<ull*>(sm + O_WHR);
    ull*   wFR = reinterpret_cast<ull*>(sm + O_WFR);
    ull*   wWC = reinterpret_cast<ull*>(sm + O_WWC);
    float* sbdh = sm + O_BDH;
    float* sbhr = sm + O_BHR;
    float* sbfr = sm + O_BFR;
    float* sbwc = sm + O_BWC;
    float* swdx = sm + O_WDX;
    float* sbdx = sm + O_BDX;
    float* sbg  = sm + O_BG;
    float* sact = sm + O_ACT;   // per row g: [cc(64) | m(64) | h(128)]
    float* sc   = sm + O_C;
    float* sxb  = sm + O_XBUF;  // double buffer
    float* sgx  = sm + O_GX;
    float* sxc  = sm + O_XC;
    float* sg4  = sm + O_G4;

    // ---- one-time staging of small weights (k-pair packed) ----
    {
        const float2* Wdh2 = reinterpret_cast<const float2*>(W_dh);
        for (int i = tid; i < 4096; i += cNT) {
            int kp = i >> 7, j = i & 127;
            reinterpret_cast<float2*>(wDH)[kp * 128 + j] = Wdh2[j * 32 + kp];
        }
        const float2* Whr2 = reinterpret_cast<const float2*>(W_hr);
        for (int i = tid; i < 4096; i += cNT) {
            int kp = i >> 6, f = i & 63;
            reinterpret_cast<float2*>(wHR)[kp * 64 + f] = Whr2[f * 64 + kp];
        }
        const float2* Wfr2 = reinterpret_cast<const float2*>(W_fr);
        for (int i = tid; i < 2048; i += cNT) {
            int kp = i >> 6, f = i & 63;
            float2 v = Wfr2[f * 32 + kp];
            if (2 * kp == f)     v.x = 0.f;
            if (2 * kp + 1 == f) v.y = 0.f;
            reinterpret_cast<float2*>(wFR)[kp * 64 + f] = v;
        }
        const float2* Wwc2 = reinterpret_cast<const float2*>(W_wc);
        for (int i = tid; i < 4096; i += cNT) {
            int kp = i >> 6, f = i & 63;
            reinterpret_cast<float2*>(wWC)[kp * 64 + f] = Wwc2[f * 64 + kp];
        }
    }
    if (tid < cH) sbdh[tid] = b_dh[tid];
    if (tid < cF) {
        sbhr[tid] = b_hr[tid]; sbfr[tid] = b_fr[tid]; sbwc[tid] = b_wc[tid];
        sbdx[tid] = b_dx[tid]; swdx[tid] = W_dx[tid * cF + tid];
    }
    if (tid < 4 * cH) sbg[tid] = b_ih[tid] + b_hh[tid];
    { sact[tid] = 0.f; sact[512 + tid] = 0.f; sc[tid] = 0.f; }
    if (tid < cG * cF) {
        int g = tid >> 6, f = tid & 63;
        long off = ((long)(b0 + g) * cT + 0) * cF + f;
        sxb[tid] = values[off]; sxb[256 + tid] = masks[off]; sxb[512 + tid] = deltas[off];
    }
    __syncthreads();

    float loss_acc = 0.f;
    float* out_pred = out + 1;
    float* out_imp  = out + 1 + cB;

    const int gP = tid >> 6;          // 256-thread phases
    const int fP = tid & 63;
    const int gJ = tid >> 7;          // 512-thread phases
    const int jJ = tid & 127;
    const int kstart = blockIdx.x & 63;  // L2 anti-hotspot stagger

    for (int t = 0; t < cT; ++t) {
        const float minv = g_minv[t];
        float* bx = sxb + (t & 1) * 768;
        float* bm = bx + 256;
        float* bd = bx + 512;
        float* nbx = sxb + ((t & 1) ^ 1) * 768;

        float r_xv = 0.f, r_mv = 0.f, r_xh = 0.f;

        // ---- phase A (256 thr): gamma_x; x_h GEMV; loss 1; x_c
        if (tid < 256) {
            r_xv = bx[tid]; r_mv = bm[tid];
            float dv = bd[tid];
            sgx[tid] = expf(-fmaxf(dv * swdx[fP] + sbdx[fP], 0.f));
            const ull* hp = reinterpret_cast<const ull*>(sact + (gP << 8)) + 64;
            ull a = 0ull;
            #pragma unroll
            for (int kp = 0; kp < 64; ++kp) a = ffma2(wHR[kp * 64 + fP], hp[kp], a);
            r_xh = sbhr[fP] + upk_sum(a);
            loss_acc += fabsf(r_xv - r_xh) * r_mv * minv;
            sxc[tid] = r_mv * r_xv + (1.f - r_mv) * r_xh;
        }
        __syncthreads();

        // ---- phase B (256 thr): z_h, alpha, c_h, c_c; losses 2,3; imputation
        if (tid < 256) {
            const ull* xcp = reinterpret_cast<const ull*>(sxc + (gP << 6));
            const ull* gxp = reinterpret_cast<const ull*>(sgx + (gP << 6));
            const ull* mp  = reinterpret_cast<const ull*>(bm + (gP << 6));
            ull az = 0ull, aa = 0ull;
            #pragma unroll
            for (int kp = 0; kp < 32; ++kp) {
                az = ffma2(wFR[kp * 64 + fP], xcp[kp], az);
                aa = ffma2(wWC[kp * 64 + fP], gxp[kp], aa);
                aa = ffma2(wWC[(32 + kp) * 64 + fP], mp[kp], aa);
            }
            float z  = sbfr[fP] + upk_sum(az);
            float al = sbwc[fP] + upk_sum(aa);
            float ch = al * z + (1.f - al) * r_xh;
            loss_acc += (fabsf(r_xv - z) + fabsf(r_xv - ch)) * r_mv * minv;
            float cc = r_mv * r_xv + (1.f - r_mv) * ch;
            out_imp[((long)(b0 + gP) * cT + t) * cF + fP] = cc;
            sact[(gP << 8) + fP] = cc;
            sact[(gP << 8) + 64 + fP] = r_mv;
        }
        __syncthreads();

        // ---- phase C (512 thr): gates GEMV with per-block staggered k order
        {
            float px = 0.f, pm = 0.f, pd = 0.f;
            if (tid < 256) {
                int tn = (t + 1 < cT) ? (t + 1) : (cT - 1);
                long off = ((long)(b0 + gP) * cT + tn) * cF + fP;
                px = values[off]; pm = masks[off]; pd = deltas[off];
            }

            const int j = tid;
            const ulonglong2* Wp = reinterpret_cast<const ulonglong2*>(g_W4) + j;
            const ulonglong2* A0 = reinterpret_cast<const ulonglong2*>(sact);
            const ulonglong2* A1 = reinterpret_cast<const ulonglong2*>(sact + 256);
            const ulonglong2* A2 = reinterpret_cast<const ulonglong2*>(sact + 512);
            const ulonglong2* A3 = reinterpret_cast<const ulonglong2*>(sact + 768);
            ull a0 = 0ull, a1 = 0ull, a2 = 0ull, a3 = 0ull;
            ull b0a = 0ull, b1a = 0ull, b2a = 0ull, b3a = 0ull;
            int i = kstart;
            #pragma unroll 4
            for (int cix = 0; cix < 64; ++cix) {
                ulonglong2 wv = Wp[i * 512];
                ulonglong2 v0 = A0[i], v1 = A1[i], v2 = A2[i], v3 = A3[i];
                a0  = ffma2(wv.x, v0.x, a0);  b0a = ffma2(wv.y, v0.y, b0a);
                a1  = ffma2(wv.x, v1.x, a1);  b1a = ffma2(wv.y, v1.y, b1a);
                a2  = ffma2(wv.x, v2.x, a2);  b2a = ffma2(wv.y, v2.y, b2a);
                a3  = ffma2(wv.x, v3.x, a3);  b3a = ffma2(wv.y, v3.y, b3a);
                i = (i + 1) & 63;
            }
            if (tid < 256) { nbx[tid] = px; nbx[256 + tid] = pm; nbx[512 + tid] = pd; }

            float bb = sbg[j];
            sg4[j]        = bb + upk_sum(a0) + upk_sum(b0a);
            sg4[512 + j]  = bb + upk_sum(a1) + upk_sum(b1a);
            sg4[1024 + j] = bb + upk_sum(a2) + upk_sum(b2a);
            sg4[1536 + j] = bb + upk_sum(a3) + upk_sum(b3a);
        }
        __syncthreads();

        // ---- phase D (512 thr): LSTM update fused with gamma_h(d_{t+1}) decay
        {
            const float* gg = sg4 + (gJ << 9);
            float ig = 1.f / (1.f + expf(-gg[jJ]));
            float fg = 1.f / (1.f + expf(-gg[cH + jJ]));
            float gv = tanhf(gg[2 * cH + jJ]);
            float og = 1.f / (1.f + expf(-gg[3 * cH + jJ]));
            float cn = fg * sc[tid] + ig * gv;
            sc[tid] = cn;
            float hn = og * tanhf(cn);
            if (t + 1 < cT) {
                const ull* dp = reinterpret_cast<const ull*>(nbx + 512 + (gJ << 6));
                ull a = 0ull;
                #pragma unroll
                for (int kp = 0; kp < 32; ++kp) a = ffma2(wDH[kp * 128 + jJ], dp[kp], a);
                hn *= expf(-fmaxf(sbdh[jJ] + upk_sum(a), 0.f));
            }
            sact[(gJ << 8) + 128 + jJ] = hn;
        }
        __syncthreads();
    }

    // ---- deterministic x_loss block reduction
    sg4[tid] = loss_acc;
    __syncthreads();
    for (int o = cNT / 2; o > 0; o >>= 1) {
        if (tid < o) sg4[tid] += sg4[tid + o];
        __syncthreads();
    }
    if (tid == 0) g_xpart[blockIdx.x] = sg4[0];
    __syncthreads();

    // ---- classification head: one warp per batch row
    if (tid < cG * 32) {
        int g = tid >> 5, l = tid & 31;
        const float* hg = sact + (g << 8) + 128;
        float s = 0.f;
        #pragma unroll
        for (int k = l; k < cH; k += 32) s = fmaf(W_out[k], hg[k], s);
        #pragma unroll
        for (int o = 16; o > 0; o >>= 1) s += __shfl_down_sync(0xffffffffu, s, o);
        if (l == 0) {
            float yh = s + b_out[0];
            int b = b0 + g;
            out_pred[b] = 1.f / (1.f + expf(-yh));
            float mx = fmaxf(-yh, 0.f);
            float yl = yh - yh * labels[b] + mx + logf(expf(-mx) + expf(-yh - mx));
            sg4[1024 + g] = yl * is_train[b];
        }
    }
    __syncthreads();
    if (tid == 0) {
        float s = 0.f;
        for (int g = 0; g < cG; ++g) s += sg4[1024 + g];
        g_ypart[blockIdx.x] = s;
    }
}

// ---------------------------------------------------------------------------
__global__ void finalize_kernel(const float* __restrict__ is_train,
                                float* __restrict__ out) {
    if (threadIdx.x == 0 && blockIdx.x == 0) {
        float xs = 0.f, ys = 0.f;
        for (int i = 0; i < cNB; ++i) { xs += g_xpart[i]; ys += g_ypart[i]; }
        float st = 0.f;
        for (int b = 0; b < cB; ++b) st += is_train[b];
        out[0] = xs / (float)cT + (ys / (st + 1e-5f)) * 0.3f;
    }
}

// ---------------------------------------------------------------------------
extern "C" void kernel_launch(void* const* d_in, const int* in_sizes, int n_in,
                              void* d_out, int out_size) {
    const float* values   = (const float*)d_in[0];
    const float* masks    = (const float*)d_in[1];
    const float* deltas   = (const float*)d_in[2];
    const float* labels   = (const float*)d_in[3];
    const float* is_train = (const float*)d_in[4];
    const float* W_dh  = (const float*)d_in[5];
    const float* b_dh  = (const float*)d_in[6];
    const float* W_dx  = (const float*)d_in[7];
    const float* b_dx  = (const float*)d_in[8];
    const float* W_hr  = (const float*)d_in[9];
    const float* b_hr  = (const float*)d_in[10];
    const float* W_fr  = (const float*)d_in[11];
    const float* b_fr  = (const float*)d_in[12];
    const float* W_wc  = (const float*)d_in[13];
    const float* b_wc  = (const float*)d_in[14];
    const float* W_ih  = (const float*)d_in[15];
    const float* b_ih  = (const float*)d_in[16];
    const float* W_hh  = (const float*)d_in[17];
    const float* b_hh  = (const float*)d_in[18];
    const float* W_out = (const float*)d_in[19];
    const float* b_out = (const float*)d_in[20];
    float* out = (float*)d_out;

    const size_t smem_bytes = (size_t)SMEM_FLOATS * sizeof(float);
    cudaFuncSetAttribute(scan_kernel,
                         cudaFuncAttributeMaxDynamicSharedMemorySize,
                         (int)smem_bytes);

    prep_kernel<<<cT, 256>>>(masks, W_ih, W_hh);
    scan_kernel<<<cNB, cNT, smem_bytes>>>(
        values, masks, deltas, labels, is_train,
        W_dh, b_dh, W_dx, b_dx, W_hr, b_hr, W_fr, b_fr, W_wc, b_wc,
        b_ih, b_hh, W_out, b_out, out);
    finalize_kernel<<<1, 32>>>(is_train, out);
}

// round 6
// speedup vs baseline: 1.1273x; 1.1273x over previous
#include <cuda_runtime.h>
#include <math.h>

// Problem constants
constexpr int cB = 256;   // batch
constexpr int cT = 512;   // timesteps
constexpr int cF = 64;    // features
constexpr int cH = 128;   // hidden
constexpr int cG = 4;     // batch rows per block
constexpr int cNB = cB / cG;   // 64 blocks
constexpr int cNT = 512;       // threads per block

typedef unsigned long long ull;

// Device-global scratch
__device__ float  g_minv[cT];
__device__ float  g_xpart[cNB];
__device__ float  g_ypart[cNB];
// Gate weights repacked: g_W4[i][j] = float4(W[4i..4i+3][j]) for unified k in [0,256)
__device__ float4 g_W4[64 * 512];

// ---------------- packed fp32x2 helpers (Blackwell FFMA2) ----------------
__device__ __forceinline__ ull ffma2(ull a, ull b, ull c) {
    ull d;
    asm("fma.rn.f32x2 %0, %1, %2, %3;" : "=l"(d) : "l"(a), "l"(b), "l"(c));
    return d;
}
__device__ __forceinline__ float upk_sum(ull v) {
    float x, y;
    asm("mov.b64 {%0, %1}, %2;" : "=f"(x), "=f"(y) : "l"(v));
    return x + y;
}

// ---------------- shared memory layout (float offsets, all even) ----------------
constexpr int O_WDH = 0;          // ull[kp<32][j<128]   8192 fl
constexpr int O_WHR = 8192;       // ull[kp<64][f<64]    8192 fl
constexpr int O_WFR = 16384;      // ull[kp<32][f<64]    4096 fl
constexpr int O_WWC = 20480;      // ull[kp<64][f<64]    8192 fl
constexpr int O_BDH = 28672;      // 128
constexpr int O_BHR = 28800;      // 64
constexpr int O_BFR = 28864;      // 64
constexpr int O_BWC = 28928;      // 64
constexpr int O_WDX = 28992;      // 64
constexpr int O_BDX = 29056;      // 64
constexpr int O_BG  = 29120;      // 512 (b_ih+b_hh)
constexpr int O_ACT = 29632;      // [4][256]: cc(64), m(64), h(128)  1024 fl (16B aligned)
constexpr int O_C   = 30656;      // 512
constexpr int O_XBUF= 31168;      // [2][x(256), m(256), d(256)] = 1536
constexpr int O_GX  = 32704;      // 256
constexpr int O_XC  = 32960;      // 256
constexpr int O_G4  = 33216;      // 2048 (gates / reduction scratch)
constexpr int SMEM_FLOATS = O_G4 + 2048;   // 35264 floats = 141056 B

// ---------------------------------------------------------------------------
// Kernel A: per-step mask-sum inverses + gate-weight repack
// ---------------------------------------------------------------------------
__global__ void prep_kernel(const float* __restrict__ masks,
                            const float* __restrict__ W_ih,
                            const float* __restrict__ W_hh) {
    const int t = blockIdx.x;
    const int tid = threadIdx.x;

    int gid = blockIdx.x * 256 + tid;
    if (gid < 64 * 512) {
        int i = gid >> 9;          // k-group 0..63
        int j = gid & 511;         // output 0..511
        const float4* src = (i < 32)
            ? reinterpret_cast<const float4*>(W_ih) + (j * 32 + i)
            : reinterpret_cast<const float4*>(W_hh) + (j * 32 + (i - 32));
        g_W4[i * 512 + j] = *src;
    }

    __shared__ float red[256];
    float s = 0.f;
    for (int i = tid; i < cB * cF; i += 256) {
        int b = i >> 6, f = i & 63;
        s += masks[((long)b * cT + t) * cF + f];
    }
    red[tid] = s;
    __syncthreads();
    for (int o = 128; o > 0; o >>= 1) {
        if (tid < o) red[tid] += red[tid + o];
        __syncthreads();
    }
    if (tid == 0) g_minv[t] = 1.0f / (red[0] + 1e-5f);
}

// ---------------------------------------------------------------------------
// Kernel B: the recurrent scan. One block = 4 batch rows.
// ---------------------------------------------------------------------------
__global__ __launch_bounds__(cNT) void scan_kernel(
    const float* __restrict__ values, const float* __restrict__ masks,
    const float* __restrict__ deltas, const float* __restrict__ labels,
    const float* __restrict__ is_train,
    const float* __restrict__ W_dh, const float* __restrict__ b_dh,
    const float* __restrict__ W_dx, const float* __restrict__ b_dx,
    const float* __restrict__ W_hr, const float* __restrict__ b_hr,
    const float* __restrict__ W_fr, const float* __restrict__ b_fr,
    const float* __restrict__ W_wc, const float* __restrict__ b_wc,
    const float* __restrict__ b_ih, const float* __restrict__ b_hh,
    const float* __restrict__ W_out, const float* __restrict__ b_out,
    float* __restrict__ out)
{
    extern __shared__ __align__(16) float sm[];
    const int tid = threadIdx.x;
    const int b0 = blockIdx.x * cG;

    ull*   wDH = reinterpret_cast<ull*>(sm + O_WDH);
    ull*   wHR = reinterpret_cast<ull*>(sm + O_WHR);
    ull*   wFR = reinterpret_cast<ull*>(sm + O_WFR);
    ull*   wWC = reinterpret_cast<ull*>(sm + O_WWC);
    float* sbdh = sm + O_BDH;
    float* sbhr = sm + O_BHR;
    float* sbfr = sm + O_BFR;
    float* sbwc = sm + O_BWC;
    float* swdx = sm + O_WDX;
    float* sbdx = sm + O_BDX;
    float* sbg  = sm + O_BG;
    float* sact = sm + O_ACT;   // per row g: [cc(64) | m(64) | h(128)]
    float* sc   = sm + O_C;
    float* sxb  = sm + O_XBUF;  // double buffer
    float* sgx  = sm + O_GX;
    float* sxc  = sm + O_XC;
    float* sg4  = sm + O_G4;

    // ---- one-time staging of small weights (k-pair packed) ----
    {
        const float2* Wdh2 = reinterpret_cast<const float2*>(W_dh);
        for (int i = tid; i < 4096; i += cNT) {
            int kp = i >> 7, j = i & 127;
            reinterpret_cast<float2*>(wDH)[kp * 128 + j] = Wdh2[j * 32 + kp];
        }
        const float2* Whr2 = reinterpret_cast<const float2*>(W_hr);
        for (int i = tid; i < 4096; i += cNT) {
            int kp = i >> 6, f = i & 63;
            reinterpret_cast<float2*>(wHR)[kp * 64 + f] = Whr2[f * 64 + kp];
        }
        const float2* Wfr2 = reinterpret_cast<const float2*>(W_fr);
        for (int i = tid; i < 2048; i += cNT) {
            int kp = i >> 6, f = i & 63;
            float2 v = Wfr2[f * 32 + kp];
            if (2 * kp == f)     v.x = 0.f;
            if (2 * kp + 1 == f) v.y = 0.f;
            reinterpret_cast<float2*>(wFR)[kp * 64 + f] = v;
        }
        const float2* Wwc2 = reinterpret_cast<const float2*>(W_wc);
        for (int i = tid; i < 4096; i += cNT) {
            int kp = i >> 6, f = i & 63;
            reinterpret_cast<float2*>(wWC)[kp * 64 + f] = Wwc2[f * 64 + kp];
        }
    }
    if (tid < cH) sbdh[tid] = b_dh[tid];
    if (tid < cF) {
        sbhr[tid] = b_hr[tid]; sbfr[tid] = b_fr[tid]; sbwc[tid] = b_wc[tid];
        sbdx[tid] = b_dx[tid]; swdx[tid] = W_dx[tid * cF + tid];
    }
    if (tid < 4 * cH) sbg[tid] = b_ih[tid] + b_hh[tid];
    { sact[tid] = 0.f; sact[512 + tid] = 0.f; sc[tid] = 0.f; }
    if (tid < cG * cF) {
        int g = tid >> 6, f = tid & 63;
        long off = ((long)(b0 + g) * cT + 0) * cF + f;
        sxb[tid] = values[off]; sxb[256 + tid] = masks[off]; sxb[512 + tid] = deltas[off];
    }
    __syncthreads();

    float loss_acc = 0.f;
    float* out_pred = out + 1;
    float* out_imp  = out + 1 + cB;

    const int gP = tid >> 6;          // 256-thread phases
    const int fP = tid & 63;
    const int gJ = tid >> 7;          // 512-thread phases
    const int jJ = tid & 127;

    for (int t = 0; t < cT; ++t) {
        const float minv = g_minv[t];
        float* bx = sxb + (t & 1) * 768;
        float* bm = bx + 256;
        float* bd = bx + 512;
        float* nbx = sxb + ((t & 1) ^ 1) * 768;

        float r_xv = 0.f, r_mv = 0.f, r_xh = 0.f;

        // ---- phase A (256 thr): gamma_x; x_h GEMV; loss 1; x_c
        if (tid < 256) {
            r_xv = bx[tid]; r_mv = bm[tid];
            float dv = bd[tid];
            sgx[tid] = expf(-fmaxf(dv * swdx[fP] + sbdx[fP], 0.f));
            const ull* hp = reinterpret_cast<const ull*>(sact + (gP << 8)) + 64;
            ull a = 0ull;
            #pragma unroll
            for (int kp = 0; kp < 64; ++kp) a = ffma2(wHR[kp * 64 + fP], hp[kp], a);
            r_xh = sbhr[fP] + upk_sum(a);
            loss_acc += fabsf(r_xv - r_xh) * r_mv * minv;
            sxc[tid] = r_mv * r_xv + (1.f - r_mv) * r_xh;
        }
        __syncthreads();

        // ---- phase B (256 thr): z_h, alpha, c_h, c_c; losses 2,3; imputation
        if (tid < 256) {
            const ull* xcp = reinterpret_cast<const ull*>(sxc + (gP << 6));
            const ull* gxp = reinterpret_cast<const ull*>(sgx + (gP << 6));
            const ull* mp  = reinterpret_cast<const ull*>(bm + (gP << 6));
            ull az = 0ull, aa = 0ull;
            #pragma unroll
            for (int kp = 0; kp < 32; ++kp) {
                az = ffma2(wFR[kp * 64 + fP], xcp[kp], az);
                aa = ffma2(wWC[kp * 64 + fP], gxp[kp], aa);
                aa = ffma2(wWC[(32 + kp) * 64 + fP], mp[kp], aa);
            }
            float z  = sbfr[fP] + upk_sum(az);
            float al = sbwc[fP] + upk_sum(aa);
            float ch = al * z + (1.f - al) * r_xh;
            loss_acc += (fabsf(r_xv - z) + fabsf(r_xv - ch)) * r_mv * minv;
            float cc = r_mv * r_xv + (1.f - r_mv) * ch;
            out_imp[((long)(b0 + gP) * cT + t) * cF + fP] = cc;
            sact[(gP << 8) + fP] = cc;
            sact[(gP << 8) + 64 + fP] = r_mv;
        }
        __syncthreads();

        // ---- phase C (512 thr): gates GEMV, affine k-order, deep unroll
        {
            float px = 0.f, pm = 0.f, pd = 0.f;
            if (tid < 256) {
                int tn = (t + 1 < cT) ? (t + 1) : (cT - 1);
                long off = ((long)(b0 + gP) * cT + tn) * cF + fP;
                px = values[off]; pm = masks[off]; pd = deltas[off];
            }

            const int j = tid;
            const ulonglong2* Wp = reinterpret_cast<const ulonglong2*>(g_W4) + j;
            const ulonglong2* A0 = reinterpret_cast<const ulonglong2*>(sact);
            const ulonglong2* A1 = reinterpret_cast<const ulonglong2*>(sact + 256);
            const ulonglong2* A2 = reinterpret_cast<const ulonglong2*>(sact + 512);
            const ulonglong2* A3 = reinterpret_cast<const ulonglong2*>(sact + 768);
            ull a0 = 0ull, a1 = 0ull, a2 = 0ull, a3 = 0ull;
            ull b0a = 0ull, b1a = 0ull, b2a = 0ull, b3a = 0ull;
            #pragma unroll 8
            for (int i = 0; i < 64; ++i) {
                ulonglong2 wv = Wp[i * 512];
                ulonglong2 v0 = A0[i], v1 = A1[i], v2 = A2[i], v3 = A3[i];
                a0  = ffma2(wv.x, v0.x, a0);  b0a = ffma2(wv.y, v0.y, b0a);
                a1  = ffma2(wv.x, v1.x, a1);  b1a = ffma2(wv.y, v1.y, b1a);
                a2  = ffma2(wv.x, v2.x, a2);  b2a = ffma2(wv.y, v2.y, b2a);
                a3  = ffma2(wv.x, v3.x, a3);  b3a = ffma2(wv.y, v3.y, b3a);
            }
            if (tid < 256) { nbx[tid] = px; nbx[256 + tid] = pm; nbx[512 + tid] = pd; }

            float bb = sbg[j];
            sg4[j]        = bb + upk_sum(a0) + upk_sum(b0a);
            sg4[512 + j]  = bb + upk_sum(a1) + upk_sum(b1a);
            sg4[1024 + j] = bb + upk_sum(a2) + upk_sum(b2a);
            sg4[1536 + j] = bb + upk_sum(a3) + upk_sum(b3a);
        }
        __syncthreads();

        // ---- phase D (512 thr): LSTM update fused with gamma_h(d_{t+1}) decay
        {
            const float* gg = sg4 + (gJ << 9);
            float ig = 1.f / (1.f + expf(-gg[jJ]));
            float fg = 1.f / (1.f + expf(-gg[cH + jJ]));
            float gv = tanhf(gg[2 * cH + jJ]);
            float og = 1.f / (1.f + expf(-gg[3 * cH + jJ]));
            float cn = fg * sc[tid] + ig * gv;
            sc[tid] = cn;
            float hn = og * tanhf(cn);
            if (t + 1 < cT) {
                const ull* dp = reinterpret_cast<const ull*>(nbx + 512 + (gJ << 6));
                ull a = 0ull;
                #pragma unroll
                for (int kp = 0; kp < 32; ++kp) a = ffma2(wDH[kp * 128 + jJ], dp[kp], a);
                hn *= expf(-fmaxf(sbdh[jJ] + upk_sum(a), 0.f));
            }
            sact[(gJ << 8) + 128 + jJ] = hn;
        }
        __syncthreads();
    }

    // ---- deterministic x_loss block reduction
    sg4[tid] = loss_acc;
    __syncthreads();
    for (int o = cNT / 2; o > 0; o >>= 1) {
        if (tid < o) sg4[tid] += sg4[tid + o];
        __syncthreads();
    }
    if (tid == 0) g_xpart[blockIdx.x] = sg4[0];
    __syncthreads();

    // ---- classification head: one warp per batch row
    if (tid < cG * 32) {
        int g = tid >> 5, l = tid & 31;
        const float* hg = sact + (g << 8) + 128;
        float s = 0.f;
        #pragma unroll
        for (int k = l; k < cH; k += 32) s = fmaf(W_out[k], hg[k], s);
        #pragma unroll
        for (int o = 16; o > 0; o >>= 1) s += __shfl_down_sync(0xffffffffu, s, o);
        if (l == 0) {
            float yh = s + b_out[0];
            int b = b0 + g;
            out_pred[b] = 1.f / (1.f + expf(-yh));
            float mx = fmaxf(-yh, 0.f);
            float yl = yh - yh * labels[b] + mx + logf(expf(-mx) + expf(-yh - mx));
            sg4[1024 + g] = yl * is_train[b];
        }
    }
    __syncthreads();
    if (tid == 0) {
        float s = 0.f;
        for (int g = 0; g < cG; ++g) s += sg4[1024 + g];
        g_ypart[blockIdx.x] = s;
    }
}

// ---------------------------------------------------------------------------
__global__ void finalize_kernel(const float* __restrict__ is_train,
                                float* __restrict__ out) {
    if (threadIdx.x == 0 && blockIdx.x == 0) {
        float xs = 0.f, ys = 0.f;
        for (int i = 0; i < cNB; ++i) { xs += g_xpart[i]; ys += g_ypart[i]; }
        float st = 0.f;
        for (int b = 0; b < cB; ++b) st += is_train[b];
        out[0] = xs / (float)cT + (ys / (st + 1e-5f)) * 0.3f;
    }
}

// ---------------------------------------------------------------------------
extern "C" void kernel_launch(void* const* d_in, const int* in_sizes, int n_in,
                              void* d_out, int out_size) {
    const float* values   = (const float*)d_in[0];
    const float* masks    = (const float*)d_in[1];
    const float* deltas   = (const float*)d_in[2];
    const float* labels   = (const float*)d_in[3];
    const float* is_train = (const float*)d_in[4];
    const float* W_dh  = (const float*)d_in[5];
    const float* b_dh  = (const float*)d_in[6];
    const float* W_dx  = (const float*)d_in[7];
    const float* b_dx  = (const float*)d_in[8];
    const float* W_hr  = (const float*)d_in[9];
    const float* b_hr  = (const float*)d_in[10];
    const float* W_fr  = (const float*)d_in[11];
    const float* b_fr  = (const float*)d_in[12];
    const float* W_wc  = (const float*)d_in[13];
    const float* b_wc  = (const float*)d_in[14];
    const float* W_ih  = (const float*)d_in[15];
    const float* b_ih  = (const float*)d_in[16];
    const float* W_hh  = (const float*)d_in[17];
    const float* b_hh  = (const float*)d_in[18];
    const float* W_out = (const float*)d_in[19];
    const float* b_out = (const float*)d_in[20];
    float* out = (float*)d_out;

    const size_t smem_bytes = (size_t)SMEM_FLOATS * sizeof(float);
    cudaFuncSetAttribute(scan_kernel,
                         cudaFuncAttributeMaxDynamicSharedMemorySize,
                         (int)smem_bytes);

    prep_kernel<<<cT, 256>>>(masks, W_ih, W_hh);
    scan_kernel<<<cNB, cNT, smem_bytes>>>(
        values, masks, deltas, labels, is_train,
        W_dh, b_dh, W_dx, b_dx, W_hr, b_hr, W_fr, b_fr, W_wc, b_wc,
        b_ih, b_hh, W_out, b_out, out);
    finalize_kernel<<<1, 32>>>(is_train, out);
}

// round 7
// speedup vs baseline: 1.3577x; 1.2044x over previous
#include <cuda_runtime.h>
#include <math.h>

// Problem constants
constexpr int cB = 256;   // batch
constexpr int cT = 512;   // timesteps
constexpr int cF = 64;    // features
constexpr int cH = 128;   // hidden
constexpr int cG = 4;     // batch rows per block
constexpr int cNB = cB / cG;   // 64 blocks
constexpr int cNT = 512;       // threads per block

typedef unsigned long long ull;

// Device-global scratch
__device__ float  g_minv[cT];
__device__ float  g_xpart[cNB];
__device__ float  g_ypart[cNB];
// Gate weights repacked: g_W4[i][j] = float4(W[4i..4i+3][j]) for unified k in [0,256)
__device__ float4 g_W4[64 * 512];

// ---------------- packed fp32x2 helpers (Blackwell FFMA2) ----------------
__device__ __forceinline__ ull ffma2(ull a, ull b, ull c) {
    ull d;
    asm("fma.rn.f32x2 %0, %1, %2, %3;" : "=l"(d) : "l"(a), "l"(b), "l"(c));
    return d;
}
__device__ __forceinline__ float upk_sum(ull v) {
    float x, y;
    asm("mov.b64 {%0, %1}, %2;" : "=f"(x), "=f"(y) : "l"(v));
    return x + y;
}

// ---------------- shared memory layout (float offsets, all even) ----------------
constexpr int O_WDH = 0;          // ull[kp<32][j<128]   8192 fl
constexpr int O_WHR = 8192;       // ull[kp<64][f<64]    8192 fl
constexpr int O_WFR = 16384;      // ull[kp<32][f<64]    4096 fl
constexpr int O_WWC = 20480;      // ull[kp<64][f<64]    8192 fl
constexpr int O_BDH = 28672;      // 128
constexpr int O_BHR = 28800;      // 64
constexpr int O_BFR = 28864;      // 64
constexpr int O_BWC = 28928;      // 64
constexpr int O_WDX = 28992;      // 64
constexpr int O_BDX = 29056;      // 64
constexpr int O_BG  = 29120;      // 512 (b_ih+b_hh)
constexpr int O_ACT = 29632;      // [4][256]: cc(64), m(64), h(128)  1024 fl (16B aligned)
constexpr int O_C   = 30656;      // 512
constexpr int O_XBUF= 31168;      // [2][x(256), m(256), d(256)] = 1536
constexpr int O_GX  = 32704;      // 256
constexpr int O_XC  = 32960;      // 256
constexpr int O_G4  = 33216;      // 2048 (gates / reduction scratch)
constexpr int SMEM_FLOATS = O_G4 + 2048;   // 35264 floats = 141056 B

// ---------------------------------------------------------------------------
// Kernel A: per-step mask-sum inverses + gate-weight repack
// ---------------------------------------------------------------------------
__global__ void prep_kernel(const float* __restrict__ masks,
                            const float* __restrict__ W_ih,
                            const float* __restrict__ W_hh) {
    const int t = blockIdx.x;
    const int tid = threadIdx.x;

    int gid = blockIdx.x * 256 + tid;
    if (gid < 64 * 512) {
        int i = gid >> 9;          // k-group 0..63
        int j = gid & 511;         // output 0..511
        const float4* src = (i < 32)
            ? reinterpret_cast<const float4*>(W_ih) + (j * 32 + i)
            : reinterpret_cast<const float4*>(W_hh) + (j * 32 + (i - 32));
        g_W4[i * 512 + j] = *src;
    }

    __shared__ float red[256];
    float s = 0.f;
    for (int i = tid; i < cB * cF; i += 256) {
        int b = i >> 6, f = i & 63;
        s += masks[((long)b * cT + t) * cF + f];
    }
    red[tid] = s;
    __syncthreads();
    for (int o = 128; o > 0; o >>= 1) {
        if (tid < o) red[tid] += red[tid + o];
        __syncthreads();
    }
    if (tid == 0) g_minv[t] = 1.0f / (red[0] + 1e-5f);
}

// ---------------------------------------------------------------------------
// Kernel B: the recurrent scan. One block = 4 batch rows.
// ---------------------------------------------------------------------------
__global__ __launch_bounds__(cNT) void scan_kernel(
    const float* __restrict__ values, const float* __restrict__ masks,
    const float* __restrict__ deltas, const float* __restrict__ labels,
    const float* __restrict__ is_train,
    const float* __restrict__ W_dh, const float* __restrict__ b_dh,
    const float* __restrict__ W_dx, const float* __restrict__ b_dx,
    const float* __restrict__ W_hr, const float* __restrict__ b_hr,
    const float* __restrict__ W_fr, const float* __restrict__ b_fr,
    const float* __restrict__ W_wc, const float* __restrict__ b_wc,
    const float* __restrict__ b_ih, const float* __restrict__ b_hh,
    const float* __restrict__ W_out, const float* __restrict__ b_out,
    float* __restrict__ out)
{
    extern __shared__ __align__(16) float sm[];
    const int tid = threadIdx.x;
    const int b0 = blockIdx.x * cG;

    ull*   wDH = reinterpret_cast<ull*>(sm + O_WDH);
    ull*   wHR = reinterpret_cast<ull*>(sm + O_WHR);
    ull*   wFR = reinterpret_cast<ull*>(sm + O_WFR);
    ull*   wWC = reinterpret_cast<ull*>(sm + O_WWC);
    float* sbdh = sm + O_BDH;
    float* sbhr = sm + O_BHR;
    float* sbfr = sm + O_BFR;
    float* sbwc = sm + O_BWC;
    float* swdx = sm + O_WDX;
    float* sbdx = sm + O_BDX;
    float* sbg  = sm + O_BG;
    float* sact = sm + O_ACT;   // per row g: [cc(64) | m(64) | h(128)]
    float* sc   = sm + O_C;
    float* sxb  = sm + O_XBUF;  // double buffer
    float* sgx  = sm + O_GX;
    float* sxc  = sm + O_XC;
    float* sg4  = sm + O_G4;

    // ---- one-time staging of small weights (k-pair packed) ----
    {
        const float2* Wdh2 = reinterpret_cast<const float2*>(W_dh);
        for (int i = tid; i < 4096; i += cNT) {
            int kp = i >> 7, j = i & 127;
            reinterpret_cast<float2*>(wDH)[kp * 128 + j] = Wdh2[j * 32 + kp];
        }
        const float2* Whr2 = reinterpret_cast<const float2*>(W_hr);
        for (int i = tid; i < 4096; i += cNT) {
            int kp = i >> 6, f = i & 63;
            reinterpret_cast<float2*>(wHR)[kp * 64 + f] = Whr2[f * 64 + kp];
        }
        const float2* Wfr2 = reinterpret_cast<const float2*>(W_fr);
        for (int i = tid; i < 2048; i += cNT) {
            int kp = i >> 6, f = i & 63;
            float2 v = Wfr2[f * 32 + kp];
            if (2 * kp == f)     v.x = 0.f;
            if (2 * kp + 1 == f) v.y = 0.f;
            reinterpret_cast<float2*>(wFR)[kp * 64 + f] = v;
        }
        const float2* Wwc2 = reinterpret_cast<const float2*>(W_wc);
        for (int i = tid; i < 4096; i += cNT) {
            int kp = i >> 6, f = i & 63;
            reinterpret_cast<float2*>(wWC)[kp * 64 + f] = Wwc2[f * 64 + kp];
        }
    }
    if (tid < cH) sbdh[tid] = b_dh[tid];
    if (tid < cF) {
        sbhr[tid] = b_hr[tid]; sbfr[tid] = b_fr[tid]; sbwc[tid] = b_wc[tid];
        sbdx[tid] = b_dx[tid]; swdx[tid] = W_dx[tid * cF + tid];
    }
    if (tid < 4 * cH) sbg[tid] = b_ih[tid] + b_hh[tid];
    { sact[tid] = 0.f; sact[512 + tid] = 0.f; sc[tid] = 0.f; }
    if (tid < cG * cF) {
        int g = tid >> 6, f = tid & 63;
        long off = ((long)(b0 + g) * cT + 0) * cF + f;
        sxb[tid] = values[off]; sxb[256 + tid] = masks[off]; sxb[512 + tid] = deltas[off];
    }
    __syncthreads();

    float loss_acc = 0.f;
    float* out_pred = out + 1;
    float* out_imp  = out + 1 + cB;

    const int gP = tid >> 6;          // 256-thread phases
    const int fP = tid & 63;
    const int gJ = tid >> 7;          // 512-thread phases
    const int jJ = tid & 127;

    for (int t = 0; t < cT; ++t) {
        const float minv = g_minv[t];
        float* bx = sxb + (t & 1) * 768;
        float* bm = bx + 256;
        float* bd = bx + 512;
        float* nbx = sxb + ((t & 1) ^ 1) * 768;

        float r_xv = 0.f, r_mv = 0.f, r_xh = 0.f;

        // ---- phase A (256 thr): gamma_x; x_h GEMV; loss 1; x_c
        if (tid < 256) {
            r_xv = bx[tid]; r_mv = bm[tid];
            float dv = bd[tid];
            sgx[tid] = expf(-fmaxf(dv * swdx[fP] + sbdx[fP], 0.f));
            const ull* hp = reinterpret_cast<const ull*>(sact + (gP << 8)) + 64;
            ull a = 0ull;
            #pragma unroll
            for (int kp = 0; kp < 64; ++kp) a = ffma2(wHR[kp * 64 + fP], hp[kp], a);
            r_xh = sbhr[fP] + upk_sum(a);
            loss_acc += fabsf(r_xv - r_xh) * r_mv * minv;
            sxc[tid] = r_mv * r_xv + (1.f - r_mv) * r_xh;
        }
        __syncthreads();

        // ---- phase B (256 thr): z_h, alpha, c_h, c_c; losses 2,3; imputation
        if (tid < 256) {
            const ull* xcp = reinterpret_cast<const ull*>(sxc + (gP << 6));
            const ull* gxp = reinterpret_cast<const ull*>(sgx + (gP << 6));
            const ull* mp  = reinterpret_cast<const ull*>(bm + (gP << 6));
            ull az = 0ull, aa = 0ull;
            #pragma unroll
            for (int kp = 0; kp < 32; ++kp) {
                az = ffma2(wFR[kp * 64 + fP], xcp[kp], az);
                aa = ffma2(wWC[kp * 64 + fP], gxp[kp], aa);
                aa = ffma2(wWC[(32 + kp) * 64 + fP], mp[kp], aa);
            }
            float z  = sbfr[fP] + upk_sum(az);
            float al = sbwc[fP] + upk_sum(aa);
            float ch = al * z + (1.f - al) * r_xh;
            loss_acc += (fabsf(r_xv - z) + fabsf(r_xv - ch)) * r_mv * minv;
            float cc = r_mv * r_xv + (1.f - r_mv) * ch;
            out_imp[((long)(b0 + gP) * cT + t) * cF + fP] = cc;
            sact[(gP << 8) + fP] = cc;
            sact[(gP << 8) + 64 + fP] = r_mv;
        }
        __syncthreads();

        // ---- phase C (512 thr): gates GEMV with explicit rolling LDG prefetch
        {
            float px = 0.f, pm = 0.f, pd = 0.f;
            if (tid < 256) {
                int tn = (t + 1 < cT) ? (t + 1) : (cT - 1);
                long off = ((long)(b0 + gP) * cT + tn) * cF + fP;
                px = values[off]; pm = masks[off]; pd = deltas[off];
            }

            const int j = tid;
            const ulonglong2* Wp = reinterpret_cast<const ulonglong2*>(g_W4) + j;
            const ulonglong2* A0 = reinterpret_cast<const ulonglong2*>(sact);
            const ulonglong2* A1 = reinterpret_cast<const ulonglong2*>(sact + 256);
            const ulonglong2* A2 = reinterpret_cast<const ulonglong2*>(sact + 512);
            const ulonglong2* A3 = reinterpret_cast<const ulonglong2*>(sact + 768);
            ull a0 = 0ull, a1 = 0ull, a2 = 0ull, a3 = 0ull;
            ull b0a = 0ull, b1a = 0ull, b2a = 0ull, b3a = 0ull;

            constexpr int PF = 8;   // weight prefetch depth (32 regs in flight)
            ulonglong2 wbuf[PF];
            #pragma unroll
            for (int p = 0; p < PF; ++p) wbuf[p] = Wp[p * 512];

            #pragma unroll 8
            for (int i = 0; i < 64; ++i) {
                ulonglong2 wv = wbuf[i & (PF - 1)];
                if (i + PF < 64) wbuf[i & (PF - 1)] = Wp[(i + PF) * 512];
                ulonglong2 v0 = A0[i], v1 = A1[i], v2 = A2[i], v3 = A3[i];
                a0  = ffma2(wv.x, v0.x, a0);  b0a = ffma2(wv.y, v0.y, b0a);
                a1  = ffma2(wv.x, v1.x, a1);  b1a = ffma2(wv.y, v1.y, b1a);
                a2  = ffma2(wv.x, v2.x, a2);  b2a = ffma2(wv.y, v2.y, b2a);
                a3  = ffma2(wv.x, v3.x, a3);  b3a = ffma2(wv.y, v3.y, b3a);
            }
            if (tid < 256) { nbx[tid] = px; nbx[256 + tid] = pm; nbx[512 + tid] = pd; }

            float bb = sbg[j];
            sg4[j]        = bb + upk_sum(a0) + upk_sum(b0a);
            sg4[512 + j]  = bb + upk_sum(a1) + upk_sum(b1a);
            sg4[1024 + j] = bb + upk_sum(a2) + upk_sum(b2a);
            sg4[1536 + j] = bb + upk_sum(a3) + upk_sum(b3a);
        }
        __syncthreads();

        // ---- phase D (512 thr): LSTM update fused with gamma_h(d_{t+1}) decay
        {
            const float* gg = sg4 + (gJ << 9);
            float ig = 1.f / (1.f + expf(-gg[jJ]));
            float fg = 1.f / (1.f + expf(-gg[cH + jJ]));
            float gv = tanhf(gg[2 * cH + jJ]);
            float og = 1.f / (1.f + expf(-gg[3 * cH + jJ]));
            float cn = fg * sc[tid] + ig * gv;
            sc[tid] = cn;
            float hn = og * tanhf(cn);
            if (t + 1 < cT) {
                const ull* dp = reinterpret_cast<const ull*>(nbx + 512 + (gJ << 6));
                ull a = 0ull;
                #pragma unroll
                for (int kp = 0; kp < 32; ++kp) a = ffma2(wDH[kp * 128 + jJ], dp[kp], a);
                hn *= expf(-fmaxf(sbdh[jJ] + upk_sum(a), 0.f));
            }
            sact[(gJ << 8) + 128 + jJ] = hn;
        }
        __syncthreads();
    }

    // ---- deterministic x_loss block reduction
    sg4[tid] = loss_acc;
    __syncthreads();
    for (int o = cNT / 2; o > 0; o >>= 1) {
        if (tid < o) sg4[tid] += sg4[tid + o];
        __syncthreads();
    }
    if (tid == 0) g_xpart[blockIdx.x] = sg4[0];
    __syncthreads();

    // ---- classification head: one warp per batch row
    if (tid < cG * 32) {
        int g = tid >> 5, l = tid & 31;
        const float* hg = sact + (g << 8) + 128;
        float s = 0.f;
        #pragma unroll
        for (int k = l; k < cH; k += 32) s = fmaf(W_out[k], hg[k], s);
        #pragma unroll
        for (int o = 16; o > 0; o >>= 1) s += __shfl_down_sync(0xffffffffu, s, o);
        if (l == 0) {
            float yh = s + b_out[0];
            int b = b0 + g;
            out_pred[b] = 1.f / (1.f + expf(-yh));
            float mx = fmaxf(-yh, 0.f);
            float yl = yh - yh * labels[b] + mx + logf(expf(-mx) + expf(-yh - mx));
            sg4[1024 + g] = yl * is_train[b];
        }
    }
    __syncthreads();
    if (tid == 0) {
        float s = 0.f;
        for (int g = 0; g < cG; ++g) s += sg4[1024 + g];
        g_ypart[blockIdx.x] = s;
    }
}

// ---------------------------------------------------------------------------
__global__ void finalize_kernel(const float* __restrict__ is_train,
                                float* __restrict__ out) {
    if (threadIdx.x == 0 && blockIdx.x == 0) {
        float xs = 0.f, ys = 0.f;
        for (int i = 0; i < cNB; ++i) { xs += g_xpart[i]; ys += g_ypart[i]; }
        float st = 0.f;
        for (int b = 0; b < cB; ++b) st += is_train[b];
        out[0] = xs / (float)cT + (ys / (st + 1e-5f)) * 0.3f;
    }
}

// ---------------------------------------------------------------------------
extern "C" void kernel_launch(void* const* d_in, const int* in_sizes, int n_in,
                              void* d_out, int out_size) {
    const float* values   = (const float*)d_in[0];
    const float* masks    = (const float*)d_in[1];
    const float* deltas   = (const float*)d_in[2];
    const float* labels   = (const float*)d_in[3];
    const float* is_train = (const float*)d_in[4];
    const float* W_dh  = (const float*)d_in[5];
    const float* b_dh  = (const float*)d_in[6];
    const float* W_dx  = (const float*)d_in[7];
    const float* b_dx  = (const float*)d_in[8];
    const float* W_hr  = (const float*)d_in[9];
    const float* b_hr  = (const float*)d_in[10];
    const float* W_fr  = (const float*)d_in[11];
    const float* b_fr  = (const float*)d_in[12];
    const float* W_wc  = (const float*)d_in[13];
    const float* b_wc  = (const float*)d_in[14];
    const float* W_ih  = (const float*)d_in[15];
    const float* b_ih  = (const float*)d_in[16];
    const float* W_hh  = (const float*)d_in[17];
    const float* b_hh  = (const float*)d_in[18];
    const float* W_out = (const float*)d_in[19];
    const float* b_out = (const float*)d_in[20];
    float* out = (float*)d_out;

    const size_t smem_bytes = (size_t)SMEM_FLOATS * sizeof(float);
    cudaFuncSetAttribute(scan_kernel,
                         cudaFuncAttributeMaxDynamicSharedMemorySize,
                         (int)smem_bytes);

    prep_kernel<<<cT, 256>>>(masks, W_ih, W_hh);
    scan_kernel<<<cNB, cNT, smem_bytes>>>(
        values, masks, deltas, labels, is_train,
        W_dh, b_dh, W_dx, b_dx, W_hr, b_hr, W_fr, b_fr, W_wc, b_wc,
        b_ih, b_hh, W_out, b_out, out);
    finalize_kernel<<<1, 32>>>(is_train, out);
}